// round 8
// baseline (speedup 1.0000x reference)
#include <cuda_runtime.h>
#include <cuda_bf16.h>
#include <cstdint>

#define BATCH 2048
#define NCLS  1000
#define NPAD  1024
#define FDIM  128
#define TM    64
#define TN    64

// ---- device scratch ----
__device__ __nv_bfloat16 g_featb[BATCH * FDIM];
__device__ __nv_bfloat16 g_centb[NPAD * FDIM];
__device__ float g_fnorm[BATCH];
__device__ float g_cnorm[NPAD];
__device__ float g_like_part[256];

__device__ __forceinline__ uint32_t smem_u32(const void* p) {
    uint32_t a;
    asm("{ .reg .u64 t; cvta.to.shared.u64 t, %1; cvt.u32.u64 %0, t; }" : "=r"(a) : "l"(p));
    return a;
}
__device__ __forceinline__ uint32_t pack_bf16(float x, float y) {
    __nv_bfloat162 p = __float22bfloat162_rn(make_float2(x, y));
    return *(uint32_t*)&p;
}

#define CP_ASYNC16(dst, src) \
    asm volatile("cp.async.cg.shared.global [%0], [%1], 16;" :: "r"(dst), "l"(src))
#define CP_COMMIT() asm volatile("cp.async.commit_group;" ::: "memory")
#define CP_WAIT0()  asm volatile("cp.async.wait_group 0;" ::: "memory")

#define LDSM_X4(r0, r1, r2, r3, addr) \
    asm volatile("ldmatrix.sync.aligned.m8n8.x4.shared.b16 {%0,%1,%2,%3}, [%4];" \
                 : "=r"(r0), "=r"(r1), "=r"(r2), "=r"(r3) : "r"(addr))

#define MMA_BF16(c, a, b) \
    asm volatile("mma.sync.aligned.m16n8k16.row.col.f32.bf16.bf16.f32 " \
                 "{%0,%1,%2,%3}, {%4,%5,%6,%7}, {%8,%9}, {%0,%1,%2,%3};" \
                 : "+f"((c)[0]), "+f"((c)[1]), "+f"((c)[2]), "+f"((c)[3]) \
                 : "r"((a)[0]), "r"((a)[1]), "r"((a)[2]), "r"((a)[3]), \
                   "r"((b)[0]), "r"((b)[1]))

// ---- prep: bf16 convert + fp32 norms + exact fp32 likelihood partials ----
__global__ __launch_bounds__(256) void prep_kernel(
    const float* __restrict__ feat,
    const int* __restrict__ label,
    const float* __restrict__ centers)
{
    __shared__ float s_part[8];
    const int wid  = threadIdx.x >> 5;
    const int lane = threadIdx.x & 31;

    if (blockIdx.x < 256) {
        int row = blockIdx.x * 8 + wid;
        float4 v = ((const float4*)(feat + (size_t)row * FDIM))[lane];
        uint2 w = make_uint2(pack_bf16(v.x, v.y), pack_bf16(v.z, v.w));
        ((uint2*)(g_featb + (size_t)row * FDIM))[lane] = w;
        float s = v.x*v.x + v.y*v.y + v.z*v.z + v.w*v.w;
        int lb = label[row];
        float4 c = ((const float4*)(centers + (size_t)lb * FDIM))[lane];
        float dx = v.x - c.x, dy = v.y - c.y, dz = v.z - c.z, dw = v.w - c.w;
        float q = dx*dx + dy*dy + dz*dz + dw*dw;
        #pragma unroll
        for (int o = 16; o; o >>= 1) {
            s += __shfl_xor_sync(0xffffffffu, s, o);
            q += __shfl_xor_sync(0xffffffffu, q, o);
        }
        if (lane == 0) { g_fnorm[row] = s; s_part[wid] = q; }
        __syncthreads();
        if (threadIdx.x == 0) {
            float t = 0.f;
            #pragma unroll
            for (int i = 0; i < 8; i++) t += s_part[i];
            g_like_part[blockIdx.x] = t;
        }
    } else {
        int row = (blockIdx.x - 256) * 8 + wid;
        float4 v = make_float4(0.f, 0.f, 0.f, 0.f);
        if (row < NCLS) v = ((const float4*)(centers + (size_t)row * FDIM))[lane];
        uint2 w = make_uint2(pack_bf16(v.x, v.y), pack_bf16(v.z, v.w));
        ((uint2*)(g_centb + (size_t)row * FDIM))[lane] = w;
        float s = v.x*v.x + v.y*v.y + v.z*v.z + v.w*v.w;
        #pragma unroll
        for (int o = 16; o; o >>= 1) s += __shfl_xor_sync(0xffffffffu, s, o);
        if (lane == 0) g_cnorm[row] = s;
    }
}

// ---- main: 64x64 tile, 256 threads (8 warps, 32x16 warp tiles) ----
__global__ __launch_bounds__(256) void lgm_kernel(
    const int* __restrict__ label,
    float* __restrict__ out)
{
    __shared__ __align__(16) char As[TM * 256];   // XOR-swizzled, 256B row stride
    __shared__ __align__(16) char Bs[TN * 256];
    __shared__ float s_fn[TM];
    __shared__ float s_cn[TN];
    __shared__ int   s_lb[TM];

    const int tid  = threadIdx.x;
    const int lane = tid & 31;
    const int wid  = tid >> 5;
    const int rowBase = blockIdx.y * TM;
    const int colBase = blockIdx.x * TN;
    const uint32_t aBase = smem_u32(As);
    const uint32_t bBase = smem_u32(Bs);

    // fills: 1024 16B chunks per tile, 4 per thread per tile
    #pragma unroll
    for (int it = 0; it < 4; it++) {
        int idx = it * 256 + tid;
        int row = idx >> 4, chunk = idx & 15;
        uint32_t doff = row * 256 + ((chunk ^ (row & 7)) << 4);
        CP_ASYNC16(aBase + doff, g_featb + (size_t)(rowBase + row) * FDIM + chunk * 8);
        CP_ASYNC16(bBase + doff, g_centb + (size_t)(colBase + row) * FDIM + chunk * 8);
    }
    CP_COMMIT();

    // stage norms + labels while cp.async is in flight
    if (tid < TM) s_fn[tid] = g_fnorm[rowBase + tid];
    else if (tid < TM + TN) s_cn[tid - TM] = g_cnorm[colBase + (tid - TM)];
    else if (tid < TM + TN + TM) s_lb[tid - TM - TN] = label[rowBase + (tid - TM - TN)];

    // likelihood finalization by one warp of block (0,0)
    if (blockIdx.x == 0 && blockIdx.y == 0 && wid == 7) {
        float t = 0.f;
        #pragma unroll
        for (int i = 0; i < 8; i++) t += g_like_part[lane + i * 32];
        #pragma unroll
        for (int o = 16; o; o >>= 1) t += __shfl_xor_sync(0xffffffffu, t, o);
        if (lane == 0) out[2ull * BATCH * NCLS] = t * (0.5f / (float)BATCH);
    }

    CP_WAIT0();
    __syncthreads();

    // ---- HMMA mainloop: 2x4 warps, warp tile 32x16 ----
    const int wm = wid & 1;
    const int wn = wid >> 1;
    float acc[2][2][4] = {};   // [mstep][n8][d]

    #pragma unroll
    for (int ks = 0; ks < 8; ks++) {
        const int kc = ks * 2 + (lane >> 4);
        uint32_t a[2][4];
        #pragma unroll
        for (int ms = 0; ms < 2; ms++) {
            int r = wm * 32 + ms * 16 + (lane & 15);
            uint32_t addr = aBase + r * 256 + ((kc ^ (r & 7)) << 4);
            LDSM_X4(a[ms][0], a[ms][1], a[ms][2], a[ms][3], addr);
        }
        uint32_t b[2][2];
        {
            int r = wn * 16 + (lane & 15);
            uint32_t addr = bBase + r * 256 + ((kc ^ (r & 7)) << 4);
            uint32_t r0, r1, r2, r3;
            LDSM_X4(r0, r1, r2, r3, addr);
            b[0][0] = r0; b[1][0] = r1;
            b[0][1] = r2; b[1][1] = r3;
        }
        #pragma unroll
        for (int ms = 0; ms < 2; ms++)
            #pragma unroll
            for (int ns = 0; ns < 2; ns++)
                MMA_BF16(acc[ms][ns], a[ms], b[ns]);
    }

    // ---- fused epilogue ----
    float* logits = out;
    float* margin = out + (size_t)BATCH * NCLS;
    const int g  = lane >> 2;
    const int tl = lane & 3;

    #pragma unroll
    for (int ms = 0; ms < 2; ms++) {
        #pragma unroll
        for (int half = 0; half < 2; half++) {
            int rloc = wm * 32 + ms * 16 + g + half * 8;
            int r = rowBase + rloc;
            float fn = s_fn[rloc];
            int lb = s_lb[rloc];
            #pragma unroll
            for (int ns = 0; ns < 2; ns++) {
                int cloc = wn * 16 + ns * 8 + tl * 2;
                int c = colBase + cloc;
                if (c < NCLS) {   // NCLS even -> float2 all-or-nothing
                    float d0 = acc[ms][ns][half * 2];
                    float d1 = acc[ms][ns][half * 2 + 1];
                    float dist0 = fn + s_cn[cloc]     - 2.0f * d0;
                    float dist1 = fn + s_cn[cloc + 1] - 2.0f * d1;
                    float l0 = -0.5f * dist0, l1 = -0.5f * dist1;
                    float m0 = (c     == lb) ? 2.0f * l0 : l0;
                    float m1 = (c + 1 == lb) ? 2.0f * l1 : l1;
                    *(float2*)(logits + (size_t)r * NCLS + c) = make_float2(l0, l1);
                    *(float2*)(margin + (size_t)r * NCLS + c) = make_float2(m0, m1);
                }
            }
        }
    }
}

extern "C" void kernel_launch(void* const* d_in, const int* in_sizes, int n_in,
                              void* d_out, int out_size) {
    const float* feat    = (const float*)d_in[0];
    const int*   label   = (const int*)d_in[1];
    const float* centers = (const float*)d_in[2];
    float*       out     = (float*)d_out;

    prep_kernel<<<384, 256>>>(feat, label, centers);

    dim3 grid(NPAD / TN, BATCH / TM);   // 16 x 32 = 512 CTAs
    lgm_kernel<<<grid, 256>>>(label, out);
}